// round 1
// baseline (speedup 1.0000x reference)
#include <cuda_runtime.h>
#include <cuda_bf16.h>

#define BB     32
#define GG     50
#define A_TOT  8400
#define NC     80
#define TILES  33          // ceil(8400/256)
#define CRAD   2.5f

// ---------------- device scratch (statically allocated; no runtime alloc) ----------------
__device__ float4        g_bbox[BB * A_TOT];
__device__ float         g_obj [BB * A_TOT];
__device__ float         g_s   [BB * A_TOT];   // sum_c log(1-p)
__device__ float         g_sbce[BB * A_TOT];   // sum_c softplus(cls_logit)
__device__ unsigned char g_fg  [BB * A_TOT];
__device__ float         g_tg  [(size_t)BB * GG * A_TOT];   // t = logit(p) at gt class
__device__ float         g_thr [BB * GG];
__device__ double        g_acc [5];  // 0: num_fg, 1: loss_iou, 2: obj_delta(-sum obj over fg), 3: loss_cls, 4: obj_base

// ---------------- helpers ----------------
__device__ __forceinline__ void anchor_info(int a, int& lvl, int& idx, int& W, int& HW, float& stride) {
    if (a < 6400)      { lvl = 0; idx = a;        W = 80; HW = 6400; stride = 8.f;  }
    else if (a < 8000) { lvl = 1; idx = a - 6400; W = 40; HW = 1600; stride = 16.f; }
    else               { lvl = 2; idx = a - 8000; W = 20; HW = 400;  stride = 32.f; }
}

__device__ __forceinline__ float softplusf(float x) {
    float e = __expf(-fabsf(x));
    return fmaxf(x, 0.f) + __logf(1.f + e);
}

// Cost/IoU for one (gt, anchor) pair. Explicit round-to-nearest intrinsics so that
// K3 and K4 produce BITWISE-IDENTICAL costs (the cost<=thr test uses an exact cost
// value from K3; FMA-contraction drift between kernels would flip boundary matches).
__device__ __forceinline__ void pair_cost(const float4 bb,
                                          float gx, float gy, float gw, float gh,
                                          float cx, float cy, float rs,
                                          float tgv, float sA,
                                          float& cost, float& iou) {
    float bhw = __fmul_rn(bb.z, 0.5f), bhh = __fmul_rn(bb.w, 0.5f);
    float ghw = __fmul_rn(gw,   0.5f), ghh = __fmul_rn(gh,   0.5f);
    float btlx = __fsub_rn(bb.x, bhw), btly = __fsub_rn(bb.y, bhh);
    float bbrx = __fadd_rn(bb.x, bhw), bbry = __fadd_rn(bb.y, bhh);
    float gtlx = __fsub_rn(gx, ghw), gtly = __fsub_rn(gy, ghh);
    float gbrx = __fadd_rn(gx, ghw), gbry = __fadd_rn(gy, ghh);

    float tlx = fmaxf(gtlx, btlx), tly = fmaxf(gtly, btly);
    float brx = fminf(gbrx, bbrx), bry = fminf(gbry, bbry);
    bool  en  = (tlx < brx) && (tly < bry);
    float inter = en ? __fmul_rn(__fsub_rn(brx, tlx), __fsub_rn(bry, tly)) : 0.f;
    float areaB = __fmul_rn(bb.z, bb.w), areaG = __fmul_rn(gw, gh);
    float uni = __fadd_rn(__fsub_rn(__fadd_rn(areaG, areaB), inter), 1e-12f);
    iou = __fdiv_rn(inter, uni);
    float iouc = -__logf(__fadd_rn(iou, 1e-8f));

    bool inb = (cx > gtlx) && (cx < gbrx) && (cy > gtly) && (cy < gbry);
    bool inc = (fabsf(__fsub_rn(cx, gx)) < rs) && (fabsf(__fsub_rn(cy, gy)) < rs);
    float geomT = (inb && inc) ? 0.f : 1e5f;

    cost = __fadd_rn(__fadd_rn(__fsub_rn(-tgv, sA), __fmul_rn(3.f, iouc)), geomT);
}

// ---------------- K0: zero accumulators ----------------
__global__ void k0_init() {
    if (threadIdx.x < 5) g_acc[threadIdx.x] = 0.0;
}

// ---------------- K1: decode + per-anchor precompute + tg scatter + fg ----------------
__global__ void __launch_bounds__(256) k1_decode(const float* __restrict__ o0,
                                                 const float* __restrict__ o1,
                                                 const float* __restrict__ o2,
                                                 const float* __restrict__ labels) {
    __shared__ int    s_cstart[NC + 1];
    __shared__ int    s_glist[GG];
    __shared__ float  s_vg[GG][4];
    __shared__ int    s_nv;
    __shared__ double s_red[256];

    int blk = blockIdx.x;
    int b = blk / TILES, tile = blk % TILES;

    if (threadIdx.x == 0) {
        int cnt[NC];
        #pragma unroll
        for (int c = 0; c < NC; c++) cnt[c] = 0;
        int  clsArr[GG];
        bool valArr[GG];
        int nv = 0;
        for (int g = 0; g < GG; g++) {
            const float* lr = labels + (b * GG + g) * 5;
            float l0 = lr[0], l1 = lr[1], l2 = lr[2], l3 = lr[3], l4 = lr[4];
            bool v = (l0 + l1 + l2 + l3 + l4) > 0.f;
            clsArr[g] = (int)l0; valArr[g] = v;
            if (v) {
                s_vg[nv][0] = l1; s_vg[nv][1] = l2; s_vg[nv][2] = l3; s_vg[nv][3] = l4;
                cnt[(int)l0]++; nv++;
            }
        }
        s_nv = nv;
        int run = 0;
        for (int c = 0; c < NC; c++) { s_cstart[c] = run; run += cnt[c]; cnt[c] = s_cstart[c]; }
        s_cstart[NC] = run;
        for (int g = 0; g < GG; g++)
            if (valArr[g]) s_glist[cnt[clsArr[g]]++] = g;
    }
    __syncthreads();

    int a = tile * 256 + threadIdx.x;
    double objbase = 0.0;
    if (a < A_TOT) {
        int lvl, idx, W, HW; float stride;
        anchor_info(a, lvl, idx, W, HW, stride);
        const float* src = (lvl == 0) ? o0 : ((lvl == 1) ? o1 : o2);
        int base = (b * 85) * HW + idx;

        float v0 = src[base], v1 = src[base + HW], v2 = src[base + 2 * HW],
              v3 = src[base + 3 * HW], v4 = src[base + 4 * HW];
        float wq = (float)(idx % W), hq = (float)(idx / W);

        float4 bb;
        bb.x = (v0 + wq) * stride; bb.y = (v1 + hq) * stride;
        bb.z = __expf(v2) * stride; bb.w = __expf(v3) * stride;
        g_bbox[b * A_TOT + a] = bb;

        float obj = v4;
        float spo = softplusf(obj);      // bce(obj, 0)
        objbase   = (double)spo;
        g_obj[b * A_TOT + a] = obj;
        float lso = obj - spo;           // log sigmoid(obj)

        float ssum = 0.f, sbce = 0.f;
        const float* csrc = src + base + 5 * HW;
        for (int c = 0; c < NC; c++) {
            float x  = csrc[c * HW];
            float sp = softplusf(x);
            sbce += sp;
            float lpr = 0.5f * ((x - sp) + lso);   // log sqrt(sig(x) sig(obj))
            float p   = __expf(lpr);
            p = fminf(fmaxf(p, 1e-7f), 1.f - 1e-6f);
            float logp  = __logf(p);
            float l1mp  = __logf(1.f - p);
            ssum += l1mp;
            float t = logp - l1mp;
            int st = s_cstart[c], en = s_cstart[c + 1];
            for (int j = st; j < en; j++)
                g_tg[(size_t)(b * GG + s_glist[j]) * A_TOT + a] = t;
        }
        g_s   [b * A_TOT + a] = ssum;
        g_sbce[b * A_TOT + a] = sbce;

        // fg = any valid gt with (in_box | in_ctr)
        float cx = (wq + 0.5f) * stride, cy = (hq + 0.5f) * stride;
        float rs = CRAD * stride;
        bool fg = false;
        int nv = s_nv;
        for (int j = 0; j < nv; j++) {
            float gx = s_vg[j][0], gy = s_vg[j][1], gw = s_vg[j][2], gh = s_vg[j][3];
            bool inb = (cx > gx - 0.5f * gw) && (cx < gx + 0.5f * gw) &&
                       (cy > gy - 0.5f * gh) && (cy < gy + 0.5f * gh);
            bool inc = (fabsf(cx - gx) < rs) && (fabsf(cy - gy) < rs);
            fg = fg || inb || inc;
        }
        g_fg[b * A_TOT + a] = fg ? 1 : 0;
    }

    // block-reduce obj base term
    s_red[threadIdx.x] = objbase; __syncthreads();
    for (int s = 128; s > 0; s >>= 1) {
        if (threadIdx.x < s) s_red[threadIdx.x] += s_red[threadIdx.x + s];
        __syncthreads();
    }
    if (threadIdx.x == 0) atomicAdd(&g_acc[4], s_red[0]);
}

// ---------------- K3: per-GT row pass -> dyn_k threshold ----------------
__global__ void __launch_bounds__(256) k3_row(const float* __restrict__ labels) {
    int bg = blockIdx.x;
    int b = bg / GG;
    const float* lr = labels + bg * 5;
    float l0 = lr[0], l1 = lr[1], l2 = lr[2], l3 = lr[3], l4 = lr[4];
    bool valid = (l0 + l1 + l2 + l3 + l4) > 0.f;
    if (!valid) { if (threadIdx.x == 0) g_thr[bg] = -1e30f; return; }

    float gx = l1, gy = l2, gw = l3, gh = l4;

    float c10[10], i10[10];
    #pragma unroll
    for (int i = 0; i < 10; i++) { c10[i] = 3.0e38f; i10[i] = 0.f; }

    const float* tgp = g_tg + (size_t)bg * A_TOT;
    int tid = threadIdx.x;

    for (int a = tid; a < A_TOT; a += 256) {
        float4 bb = g_bbox[b * A_TOT + a];
        float  sA = g_s   [b * A_TOT + a];
        float  tgv = tgp[a];
        bool   fgA = g_fg[b * A_TOT + a] != 0;
        int lvl, idx, W, HW; float stride;
        anchor_info(a, lvl, idx, W, HW, stride);
        float cx = ((float)(idx % W) + 0.5f) * stride;
        float cy = ((float)(idx / W) + 0.5f) * stride;
        float rs = CRAD * stride;

        float cost, iou;
        pair_cost(bb, gx, gy, gw, gh, cx, cy, rs, tgv, sA, cost, iou);
        float costF = fgA ? cost : __fadd_rn(cost, 1e9f);
        float ioum  = fgA ? iou : 0.f;

        if (costF < c10[9]) {
            c10[9] = costF;
            #pragma unroll
            for (int i = 9; i > 0; i--)
                if (c10[i] < c10[i - 1]) { float t = c10[i]; c10[i] = c10[i - 1]; c10[i - 1] = t; }
        }
        if (ioum > i10[9]) {
            i10[9] = ioum;
            #pragma unroll
            for (int i = 9; i > 0; i--)
                if (i10[i] > i10[i - 1]) { float t = i10[i]; i10[i] = i10[i - 1]; i10[i - 1] = t; }
        }
    }

    __shared__ float sc[256 * 10];
    __shared__ float si[256 * 10];
    #pragma unroll
    for (int i = 0; i < 10; i++) { sc[tid * 10 + i] = c10[i]; si[tid * 10 + i] = i10[i]; }

    for (int s = 1; s < 256; s <<= 1) {
        __syncthreads();
        if ((tid & (2 * s - 1)) == 0) {
            {   // min-merge of two ascending 10-lists
                float tmp[10]; int ia = 0, ib = 0;
                float* Aay = &sc[tid * 10]; float* Bay = &sc[(tid + s) * 10];
                #pragma unroll
                for (int i = 0; i < 10; i++) {
                    float va = Aay[ia], vb = Bay[ib];
                    if (va <= vb) { tmp[i] = va; ia++; } else { tmp[i] = vb; ib++; }
                }
                #pragma unroll
                for (int i = 0; i < 10; i++) Aay[i] = tmp[i];
            }
            {   // max-merge of two descending 10-lists
                float tmp[10]; int ia = 0, ib = 0;
                float* Aay = &si[tid * 10]; float* Bay = &si[(tid + s) * 10];
                #pragma unroll
                for (int i = 0; i < 10; i++) {
                    float va = Aay[ia], vb = Bay[ib];
                    if (va >= vb) { tmp[i] = va; ia++; } else { tmp[i] = vb; ib++; }
                }
                #pragma unroll
                for (int i = 0; i < 10; i++) Aay[i] = tmp[i];
            }
        }
    }
    __syncthreads();
    if (tid == 0) {
        float ssum = 0.f;
        #pragma unroll
        for (int i = 0; i < 10; i++) ssum += si[i];
        int k = (int)ssum; if (k < 1) k = 1;
        g_thr[bg] = sc[k - 1];
    }
}

// ---------------- K4: per-anchor column pass -> matching + loss accumulation ----------------
__global__ void __launch_bounds__(256) k4_col(const float* __restrict__ o0,
                                              const float* __restrict__ o1,
                                              const float* __restrict__ o2,
                                              const float* __restrict__ labels) {
    __shared__ float  s_g[GG][4];
    __shared__ int    s_cls[GG];
    __shared__ int    s_orig[GG];
    __shared__ float  s_thr[GG];
    __shared__ int    s_nv;
    __shared__ double s_red[256];

    int blk = blockIdx.x;
    int b = blk / TILES, tile = blk % TILES;

    if (threadIdx.x == 0) {
        int nv = 0;
        for (int g = 0; g < GG; g++) {
            const float* lr = labels + (b * GG + g) * 5;
            float l0 = lr[0], l1 = lr[1], l2 = lr[2], l3 = lr[3], l4 = lr[4];
            if ((l0 + l1 + l2 + l3 + l4) > 0.f) {
                s_g[nv][0] = l1; s_g[nv][1] = l2; s_g[nv][2] = l3; s_g[nv][3] = l4;
                s_cls[nv] = (int)l0; s_orig[nv] = g; s_thr[nv] = g_thr[b * GG + g];
                nv++;
            }
        }
        s_nv = nv;
    }
    __syncthreads();

    int a = tile * 256 + threadIdx.x;
    double r_nfg = 0.0, r_liou = 0.0, r_lobj = 0.0, r_lcls = 0.0;

    if (a < A_TOT && g_fg[b * A_TOT + a]) {
        float4 bb  = g_bbox[b * A_TOT + a];
        float  obj = g_obj [b * A_TOT + a];
        float  sA  = g_s   [b * A_TOT + a];
        float  sbce = g_sbce[b * A_TOT + a];
        int lvl, idx, W, HW; float stride;
        anchor_info(a, lvl, idx, W, HW, stride);
        float cx = ((float)(idx % W) + 0.5f) * stride;
        float cy = ((float)(idx / W) + 0.5f) * stride;
        float rs = CRAD * stride;

        int cnt = 0, firstG = -1, aminG = -1;
        float firstIou = 0.f, aminIou = 0.f;
        bool aminM = false;
        float minCost = 3.4e38f;
        int nv = s_nv;

        for (int j = 0; j < nv; j++) {
            float gx = s_g[j][0], gy = s_g[j][1], gw = s_g[j][2], gh = s_g[j][3];
            float tgv = g_tg[(size_t)(b * GG + s_orig[j]) * A_TOT + a];
            float cost, iou;
            pair_cost(bb, gx, gy, gw, gh, cx, cy, rs, tgv, sA, cost, iou);
            bool m = (cost <= s_thr[j]);          // cand is true: fg anchor, valid gt
            if (m) { if (cnt == 0) { firstG = j; firstIou = iou; } cnt++; }
            if (cost < minCost) { minCost = cost; aminG = j; aminIou = iou; aminM = m; }
        }

        bool fgfin = false; int sel = 0; float piou = 0.f;
        if (cnt == 1)      { fgfin = true; sel = firstG; piou = firstIou; }
        else if (cnt > 1)  { if (aminM) { fgfin = true; sel = aminG; piou = aminIou; } }

        if (fgfin) {
            r_nfg = 1.0;
            float gx = s_g[sel][0], gy = s_g[sel][1], gw = s_g[sel][2], gh = s_g[sel][3];
            float btlx = bb.x - 0.5f * bb.z, btly = bb.y - 0.5f * bb.w;
            float bbrx = bb.x + 0.5f * bb.z, bbry = bb.y + 0.5f * bb.w;
            float tlx = fmaxf(gx - 0.5f * gw, btlx), tly = fmaxf(gy - 0.5f * gh, btly);
            float brx = fminf(gx + 0.5f * gw, bbrx), bry = fminf(gy + 0.5f * gh, bbry);
            bool  en  = (tlx < brx) && (tly < bry);
            float inter = fmaxf(brx - tlx, 0.f) * fmaxf(bry - tly, 0.f) * (en ? 1.f : 0.f);
            float uni = bb.z * bb.w + gw * gh - inter + 1e-16f;
            float iouL = inter / uni;
            r_liou = (double)(1.f - iouL * iouL);
            r_lobj = (double)(-obj);
            int mcls = s_cls[sel];
            const float* src = (lvl == 0) ? o0 : ((lvl == 1) ? o1 : o2);
            float xg = src[(b * 85 + 5 + mcls) * HW + idx];
            r_lcls = (double)(sbce - xg * piou);
        }
    }

    // 4 block reductions with one shared buffer
    double vals[4] = { r_nfg, r_liou, r_lobj, r_lcls };
    #pragma unroll
    for (int q = 0; q < 4; q++) {
        s_red[threadIdx.x] = vals[q]; __syncthreads();
        for (int s = 128; s > 0; s >>= 1) {
            if (threadIdx.x < s) s_red[threadIdx.x] += s_red[threadIdx.x + s];
            __syncthreads();
        }
        if (threadIdx.x == 0) atomicAdd(&g_acc[q], s_red[0]);
        __syncthreads();
    }
}

// ---------------- K5: combine ----------------
__global__ void k5_final(float* __restrict__ out) {
    double nfg = g_acc[0]; if (nfg < 1.0) nfg = 1.0;
    double loss_iou = g_acc[1] / nfg;
    double loss_obj = (g_acc[4] + g_acc[2]) / nfg;   // sum softplus(obj) - sum_fg obj
    double loss_cls = g_acc[3] / nfg;
    out[0] = (float)(5.0 * loss_iou + loss_obj + loss_cls);
}

// ---------------- launch ----------------
extern "C" void kernel_launch(void* const* d_in, const int* in_sizes, int n_in,
                              void* d_out, int out_size) {
    const float *o0 = nullptr, *o1 = nullptr, *o2 = nullptr, *lab = nullptr;
    for (int i = 0; i < n_in; i++) {
        int sz = in_sizes[i];
        if      (sz == BB * 85 * 6400) o0  = (const float*)d_in[i];
        else if (sz == BB * 85 * 1600) o1  = (const float*)d_in[i];
        else if (sz == BB * 85 * 400)  o2  = (const float*)d_in[i];
        else if (sz == BB * GG * 5)    lab = (const float*)d_in[i];
    }

    k0_init<<<1, 32>>>();
    k1_decode<<<BB * TILES, 256>>>(o0, o1, o2, lab);
    k3_row<<<BB * GG, 256>>>(lab);
    k4_col<<<BB * TILES, 256>>>(o0, o1, o2, lab);
    k5_final<<<1, 1>>>((float*)d_out);
}

// round 4
// speedup vs baseline: 1.7893x; 1.7893x over previous
#include <cuda_runtime.h>
#include <cuda_bf16.h>

#define BB     32
#define GG     50
#define A_TOT  8400
#define NC     80
#define TILES  33          // ceil(8400/256)
#define CRAD   2.5f
#define CAP    8400        // max fg slots per image (worst case)

// ---------------- device scratch (static; no runtime alloc) ----------------
__device__ int    g_nv[BB];
__device__ float4 g_gt[BB][GG];          // compacted valid gt boxes (cx,cy,w,h)
__device__ int    g_gcls[BB][GG];        // compacted gt class
__device__ int    g_cstart[BB][NC + 1];  // class -> compact-gt inverted list
__device__ int    g_glist[BB][GG];
__device__ int    g_fgcnt[BB];

__device__ float4 c_bbox[BB * CAP];
__device__ float  c_s   [BB * CAP];      // sum_c log(1-p)
__device__ float  c_sbce[BB * CAP];      // sum_c softplus(cls logit)
__device__ float  c_obj [BB * CAP];
__device__ int    c_a   [BB * CAP];      // original anchor id

__device__ float  g_tgc [(size_t)BB * GG * CAP];  // t=logit(p) at gt class, [b][j][slot]
__device__ float  g_thrj[BB * GG];
__device__ double g_acc [5];  // 0 num_fg, 1 loss_iou, 2 -sum_fg obj, 3 loss_cls, 4 sum softplus(obj)

// ---------------- helpers ----------------
__device__ __forceinline__ void anchor_info(int a, int& lvl, int& idx, int& W, int& HW, float& stride) {
    if (a < 6400)      { lvl = 0; idx = a;        W = 80; HW = 6400; stride = 8.f;  }
    else if (a < 8000) { lvl = 1; idx = a - 6400; W = 40; HW = 1600; stride = 16.f; }
    else               { lvl = 2; idx = a - 8000; W = 20; HW = 400;  stride = 32.f; }
}

__device__ __forceinline__ float softplusf(float x) {
    float e = __expf(-fabsf(x));
    return fmaxf(x, 0.f) + __logf(1.f + e);
}

// Cost/IoU for one (gt, anchor) pair. Explicit round-to-nearest intrinsics so K3 and K4
// produce BITWISE-IDENTICAL costs (K4 tests cost<=thr against K3's exact stored value).
__device__ __forceinline__ void pair_cost(const float4 bb,
                                          float gx, float gy, float gw, float gh,
                                          float cx, float cy, float rs,
                                          float tgv, float sA,
                                          float& cost, float& iou) {
    float bhw = __fmul_rn(bb.z, 0.5f), bhh = __fmul_rn(bb.w, 0.5f);
    float ghw = __fmul_rn(gw,   0.5f), ghh = __fmul_rn(gh,   0.5f);
    float btlx = __fsub_rn(bb.x, bhw), btly = __fsub_rn(bb.y, bhh);
    float bbrx = __fadd_rn(bb.x, bhw), bbry = __fadd_rn(bb.y, bhh);
    float gtlx = __fsub_rn(gx, ghw), gtly = __fsub_rn(gy, ghh);
    float gbrx = __fadd_rn(gx, ghw), gbry = __fadd_rn(gy, ghh);

    float tlx = fmaxf(gtlx, btlx), tly = fmaxf(gtly, btly);
    float brx = fminf(gbrx, bbrx), bry = fminf(gbry, bbry);
    bool  en  = (tlx < brx) && (tly < bry);
    float inter = en ? __fmul_rn(__fsub_rn(brx, tlx), __fsub_rn(bry, tly)) : 0.f;
    float areaB = __fmul_rn(bb.z, bb.w), areaG = __fmul_rn(gw, gh);
    float uni = __fadd_rn(__fsub_rn(__fadd_rn(areaG, areaB), inter), 1e-12f);
    iou = __fdiv_rn(inter, uni);
    float iouc = -__logf(__fadd_rn(iou, 1e-8f));

    bool inb = (cx > gtlx) && (cx < gbrx) && (cy > gtly) && (cy < gbry);
    bool inc = (fabsf(__fsub_rn(cx, gx)) < rs) && (fabsf(__fsub_rn(cy, gy)) < rs);
    float geomT = (inb && inc) ? 0.f : 1e5f;

    cost = __fadd_rn(__fadd_rn(__fsub_rn(-tgv, sA), __fmul_rn(3.f, iouc)), geomT);
}

// ---------------- KL: init + label preprocessing (one block per batch) ----------------
__global__ void kL_labels(const float* __restrict__ labels) {
    int b = blockIdx.x;
    int t = threadIdx.x;
    if (t == 1) g_fgcnt[b] = 0;
    if (b == 0 && t >= 2 && t < 7) g_acc[t - 2] = 0.0;
    if (t != 0) return;

    int cnt[NC];
    #pragma unroll
    for (int c = 0; c < NC; c++) cnt[c] = 0;
    int nv = 0;
    for (int g = 0; g < GG; g++) {
        const float* lr = labels + (b * GG + g) * 5;
        float l0 = lr[0], l1 = lr[1], l2 = lr[2], l3 = lr[3], l4 = lr[4];
        if ((l0 + l1 + l2 + l3 + l4) > 0.f) {
            float4 gb; gb.x = l1; gb.y = l2; gb.z = l3; gb.w = l4;
            g_gt[b][nv] = gb;
            int c = (int)l0;
            g_gcls[b][nv] = c;
            cnt[c]++;
            nv++;
        }
    }
    g_nv[b] = nv;
    int run = 0;
    for (int c = 0; c < NC; c++) { g_cstart[b][c] = run; run += cnt[c]; cnt[c] = g_cstart[b][c]; }
    g_cstart[b][NC] = run;
    for (int j = 0; j < nv; j++) {
        int c = g_gcls[b][j];
        g_glist[b][cnt[c]++] = j;
    }
}

// ---------------- K1: decode + fg test + compaction + class math (fg only) ----------------
__global__ void __launch_bounds__(256) k1_decode(const float* __restrict__ o0,
                                                 const float* __restrict__ o1,
                                                 const float* __restrict__ o2) {
    __shared__ float4 s_gt[GG];
    __shared__ int    s_cstart[NC + 1];
    __shared__ int    s_glist[GG];
    __shared__ int    s_nv;
    __shared__ double s_red[256];

    int blk = blockIdx.x;
    int b = blk / TILES, tile = blk % TILES;
    int tid = threadIdx.x;

    if (tid < NC + 1) s_cstart[tid] = g_cstart[b][tid];
    if (tid < GG)     { s_gt[tid] = g_gt[b][tid]; s_glist[tid] = g_glist[b][tid]; }
    if (tid == 0)     s_nv = g_nv[b];
    __syncthreads();

    int a = tile * 256 + tid;
    bool act = (a < A_TOT);
    double objbase = 0.0;

    int lvl = 0, idx = 0, W = 0, HW = 0; float stride = 0.f;
    const float* src = o0;
    float4 bb; float obj = 0.f, spo = 0.f, cx = 0.f, cy = 0.f;
    bool fg = false;
    int base = 0;

    if (act) {
        anchor_info(a, lvl, idx, W, HW, stride);
        src = (lvl == 0) ? o0 : ((lvl == 1) ? o1 : o2);
        base = (b * 85) * HW + idx;

        float v0 = src[base], v1 = src[base + HW], v2 = src[base + 2 * HW],
              v3 = src[base + 3 * HW], v4 = src[base + 4 * HW];
        float wq = (float)(idx % W), hq = (float)(idx / W);

        bb.x = (v0 + wq) * stride; bb.y = (v1 + hq) * stride;
        bb.z = __expf(v2) * stride; bb.w = __expf(v3) * stride;

        obj = v4;
        spo = softplusf(obj);
        objbase = (double)spo;

        cx = (wq + 0.5f) * stride; cy = (hq + 0.5f) * stride;
        float rs = CRAD * stride;
        int nv = s_nv;
        for (int j = 0; j < nv; j++) {
            float4 G = s_gt[j];
            bool inb = (cx > G.x - 0.5f * G.z) && (cx < G.x + 0.5f * G.z) &&
                       (cy > G.y - 0.5f * G.w) && (cy < G.y + 0.5f * G.w);
            bool inc = (fabsf(cx - G.x) < rs) && (fabsf(cy - G.y) < rs);
            fg = fg || inb || inc;
        }
    }

    // warp-aggregated slot allocation
    unsigned mask = __ballot_sync(0xffffffff, fg);
    int slot = -1;
    if (fg) {
        int lane = tid & 31;
        int leader = __ffs(mask) - 1;
        int base_s = 0;
        if (lane == leader) base_s = atomicAdd(&g_fgcnt[b], __popc(mask));
        base_s = __shfl_sync(mask, base_s, leader);
        slot = base_s + __popc(mask & ((1u << lane) - 1));
    }

    if (fg) {
        float lso = obj - spo;   // log sigmoid(obj)
        float ssum = 0.f, sbce = 0.f;
        const float* csrc = src + base + 5 * HW;
        const float LPC_LO = -16.118095651f;   // log(1e-7)
        const float LPC_HI = -1.0000005e-6f;   // log(1-1e-6)
        size_t trow = (size_t)b * GG * CAP + slot;
        for (int c = 0; c < NC; c++) {
            float x  = csrc[c * HW];
            float sp = softplusf(x);
            sbce += sp;
            float lpr = 0.5f * ((x - sp) + lso);
            lpr = fminf(fmaxf(lpr, LPC_LO), LPC_HI);
            float p    = __expf(lpr);
            float l1mp = __logf(1.f - p);
            ssum += l1mp;
            int st = s_cstart[c], en = s_cstart[c + 1];
            float t = lpr - l1mp;
            for (int q = st; q < en; q++)
                g_tgc[trow + (size_t)s_glist[q] * CAP] = t;
        }
        int mi = b * CAP + slot;
        c_bbox[mi] = bb; c_s[mi] = ssum; c_sbce[mi] = sbce; c_obj[mi] = obj; c_a[mi] = a;
    }

    // block-reduce objectness base term
    s_red[tid] = objbase; __syncthreads();
    for (int s = 128; s > 0; s >>= 1) {
        if (tid < s) s_red[tid] += s_red[tid + s];
        __syncthreads();
    }
    if (tid == 0) atomicAdd(&g_acc[4], s_red[0]);
}

// ---------------- K3: per-(b,gt) bottom-10 cost / top-10 iou over fg candidates ----------------
__global__ void __launch_bounds__(128) k3_row() {
    int b = blockIdx.y, j = blockIdx.x;
    if (j >= g_nv[b]) return;
    int cnt = g_fgcnt[b];
    float4 G = g_gt[b][j];
    int tid = threadIdx.x;

    float c10[10], i10[10];
    #pragma unroll
    for (int i = 0; i < 10; i++) { c10[i] = 3.0e38f; i10[i] = 0.f; }

    const float* tgp = g_tgc + (size_t)(b * GG + j) * CAP;
    for (int slot = tid; slot < cnt; slot += 128) {
        float4 bb = c_bbox[b * CAP + slot];
        float  sA = c_s   [b * CAP + slot];
        float  tgv = tgp[slot];
        int a = c_a[b * CAP + slot];
        int lvl, idx, W, HW; float stride;
        anchor_info(a, lvl, idx, W, HW, stride);
        float cx = ((float)(idx % W) + 0.5f) * stride;
        float cy = ((float)(idx / W) + 0.5f) * stride;
        float rs = CRAD * stride;

        float cost, iou;
        pair_cost(bb, G.x, G.y, G.z, G.w, cx, cy, rs, tgv, sA, cost, iou);

        if (cost < c10[9]) {
            c10[9] = cost;
            #pragma unroll
            for (int i = 9; i > 0; i--)
                if (c10[i] < c10[i - 1]) { float t = c10[i]; c10[i] = c10[i - 1]; c10[i - 1] = t; }
        }
        if (iou > i10[9]) {
            i10[9] = iou;
            #pragma unroll
            for (int i = 9; i > 0; i--)
                if (i10[i] > i10[i - 1]) { float t = i10[i]; i10[i] = i10[i - 1]; i10[i - 1] = t; }
        }
    }

    __shared__ float sc[128 * 10];
    __shared__ float si[128 * 10];
    #pragma unroll
    for (int i = 0; i < 10; i++) { sc[tid * 10 + i] = c10[i]; si[tid * 10 + i] = i10[i]; }

    for (int s = 1; s < 128; s <<= 1) {
        __syncthreads();
        if ((tid & (2 * s - 1)) == 0) {
            {   // min-merge ascending
                float tmp[10]; int ia = 0, ib = 0;
                float* Aay = &sc[tid * 10]; float* Bay = &sc[(tid + s) * 10];
                #pragma unroll
                for (int i = 0; i < 10; i++) {
                    float va = Aay[ia], vb = Bay[ib];
                    if (va <= vb) { tmp[i] = va; ia++; } else { tmp[i] = vb; ib++; }
                }
                #pragma unroll
                for (int i = 0; i < 10; i++) Aay[i] = tmp[i];
            }
            {   // max-merge descending
                float tmp[10]; int ia = 0, ib = 0;
                float* Aay = &si[tid * 10]; float* Bay = &si[(tid + s) * 10];
                #pragma unroll
                for (int i = 0; i < 10; i++) {
                    float va = Aay[ia], vb = Bay[ib];
                    if (va >= vb) { tmp[i] = va; ia++; } else { tmp[i] = vb; ib++; }
                }
                #pragma unroll
                for (int i = 0; i < 10; i++) Aay[i] = tmp[i];
            }
        }
    }
    __syncthreads();
    if (tid == 0) {
        float ssum = 0.f;
        #pragma unroll
        for (int i = 0; i < 10; i++) ssum += si[i];
        int k = (int)ssum; if (k < 1) k = 1;
        g_thrj[b * GG + j] = sc[k - 1];
    }
}

// ---------------- K4: per-candidate matching + loss accumulation ----------------
__global__ void __launch_bounds__(256) k4_col(const float* __restrict__ o0,
                                              const float* __restrict__ o1,
                                              const float* __restrict__ o2) {
    int b = blockIdx.y;
    int cnt = g_fgcnt[b];
    if ((int)blockIdx.x * 256 >= cnt) return;

    __shared__ float4 s_gt[GG];
    __shared__ int    s_cls[GG];
    __shared__ float  s_thr[GG];
    __shared__ int    s_nv;
    __shared__ double s_red[256];

    int tid = threadIdx.x;
    if (tid < GG) { s_gt[tid] = g_gt[b][tid]; s_cls[tid] = g_gcls[b][tid]; s_thr[tid] = g_thrj[b * GG + tid]; }
    if (tid == 0) s_nv = g_nv[b];
    __syncthreads();

    int slot = blockIdx.x * 256 + tid;
    double r_nfg = 0.0, r_liou = 0.0, r_lobj = 0.0, r_lcls = 0.0;

    if (slot < cnt) {
        float4 bb  = c_bbox[b * CAP + slot];
        float  sA  = c_s   [b * CAP + slot];
        float  sbce = c_sbce[b * CAP + slot];
        float  obj  = c_obj [b * CAP + slot];
        int a = c_a[b * CAP + slot];
        int lvl, idx, W, HW; float stride;
        anchor_info(a, lvl, idx, W, HW, stride);
        float cx = ((float)(idx % W) + 0.5f) * stride;
        float cy = ((float)(idx / W) + 0.5f) * stride;
        float rs = CRAD * stride;

        int cnt_m = 0, firstG = -1, aminG = -1;
        float firstIou = 0.f, aminIou = 0.f;
        bool aminM = false;
        float minCost = 3.4e38f;
        int nv = s_nv;
        size_t trow = (size_t)b * GG * CAP + slot;

        for (int j = 0; j < nv; j++) {
            float4 G = s_gt[j];
            float tgv = g_tgc[trow + (size_t)j * CAP];
            float cost, iou;
            pair_cost(bb, G.x, G.y, G.z, G.w, cx, cy, rs, tgv, sA, cost, iou);
            bool m = (cost <= s_thr[j]);
            if (m) { if (cnt_m == 0) { firstG = j; firstIou = iou; } cnt_m++; }
            if (cost < minCost) { minCost = cost; aminG = j; aminIou = iou; aminM = m; }
        }

        bool fgfin = false; int sel = 0; float piou = 0.f;
        if (cnt_m == 1)     { fgfin = true; sel = firstG; piou = firstIou; }
        else if (cnt_m > 1) { if (aminM) { fgfin = true; sel = aminG; piou = aminIou; } }

        if (fgfin) {
            r_nfg = 1.0;
            float4 G = s_gt[sel];
            float btlx = bb.x - 0.5f * bb.z, btly = bb.y - 0.5f * bb.w;
            float bbrx = bb.x + 0.5f * bb.z, bbry = bb.y + 0.5f * bb.w;
            float tlx = fmaxf(G.x - 0.5f * G.z, btlx), tly = fmaxf(G.y - 0.5f * G.w, btly);
            float brx = fminf(G.x + 0.5f * G.z, bbrx), bry = fminf(G.y + 0.5f * G.w, bbry);
            bool  en  = (tlx < brx) && (tly < bry);
            float inter = fmaxf(brx - tlx, 0.f) * fmaxf(bry - tly, 0.f) * (en ? 1.f : 0.f);
            float uni = bb.z * bb.w + G.z * G.w - inter + 1e-16f;
            float iouL = inter / uni;
            r_liou = (double)(1.f - iouL * iouL);
            r_lobj = (double)(-obj);
            int mcls = s_cls[sel];
            const float* src = (lvl == 0) ? o0 : ((lvl == 1) ? o1 : o2);
            float xg = src[(b * 85 + 5 + mcls) * HW + idx];
            r_lcls = (double)(sbce - xg * piou);
        }
    }

    double vals[4] = { r_nfg, r_liou, r_lobj, r_lcls };
    #pragma unroll
    for (int q = 0; q < 4; q++) {
        s_red[tid] = vals[q]; __syncthreads();
        for (int s = 128; s > 0; s >>= 1) {
            if (tid < s) s_red[tid] += s_red[tid + s];
            __syncthreads();
        }
        if (tid == 0) atomicAdd(&g_acc[q], s_red[0]);
        __syncthreads();
    }
}

// ---------------- K5: combine ----------------
__global__ void k5_final(float* __restrict__ out) {
    double nfg = g_acc[0]; if (nfg < 1.0) nfg = 1.0;
    double loss_iou = g_acc[1] / nfg;
    double loss_obj = (g_acc[4] + g_acc[2]) / nfg;
    double loss_cls = g_acc[3] / nfg;
    out[0] = (float)(5.0 * loss_iou + loss_obj + loss_cls);
}

// ---------------- launch ----------------
extern "C" void kernel_launch(void* const* d_in, const int* in_sizes, int n_in,
                              void* d_out, int out_size) {
    const float *o0 = nullptr, *o1 = nullptr, *o2 = nullptr, *lab = nullptr;
    for (int i = 0; i < n_in; i++) {
        int sz = in_sizes[i];
        if      (sz == BB * 85 * 6400) o0  = (const float*)d_in[i];
        else if (sz == BB * 85 * 1600) o1  = (const float*)d_in[i];
        else if (sz == BB * 85 * 400)  o2  = (const float*)d_in[i];
        else if (sz == BB * GG * 5)    lab = (const float*)d_in[i];
    }

    kL_labels<<<BB, 32>>>(lab);
    k1_decode<<<BB * TILES, 256>>>(o0, o1, o2);
    {
        dim3 g3(GG, BB);
        k3_row<<<g3, 128>>>();
    }
    {
        dim3 g4(TILES, BB);
        k4_col<<<g4, 256>>>(o0, o1, o2);
    }
    k5_final<<<1, 1>>>((float*)d_out);
}